// round 8
// baseline (speedup 1.0000x reference)
#include <cuda_runtime.h>
#include <cuda.h>
#include <cuda_fp16.h>
#include <cstdint>

#define NL 16
#define NB 4096
#define NH 1024
#define BM 128
#define BN 128
#define KC 64                 // fp16 elements per K chunk (= 128 bytes = SW128 row)
#define NCHUNK (NH / KC)      // 16
#define NSTAGE 5
#define MT_MAX (NB / BM)      // 32

#define STAGE_BYTES 32768     // A 16384 + B 16384
#define OFF_A  0
#define OFF_B  16384
#define SMEM_STAGE0 1024
#define SMEM_DYN_TOTAL (SMEM_STAGE0 + NSTAGE * STAGE_BYTES)   // 164864 -> 1 CTA/SM

#define SW128(off) ((off) ^ (((off) >> 3) & 0x70))

// ------------------------- device scratch (no allocs) -----------------------
__device__ int g_count[NL];
__device__ int g_offset[NL];
__device__ int g_perm[NB];
__device__ __half g_e[(size_t)NL * NH * NH];   // 32 MB : E = W - I in fp16
__device__ __half g_z[(size_t)NB * NH];        // 8 MB  : bucket-gathered z fp16

// ------------------------------ PTX helpers ---------------------------------
__device__ __forceinline__ uint32_t smem_u32(const void* p) {
    uint32_t a;
    asm("{ .reg .u64 t; cvta.to.shared.u64 t, %1; cvt.u32.u64 %0, t; }" : "=r"(a) : "l"(p));
    return a;
}

#define MBARRIER_INIT(addr, cnt) \
    asm volatile("mbarrier.init.shared.b64 [%0], %1;" :: "r"((uint32_t)(addr)), "r"((uint32_t)(cnt)) : "memory")
#define MBARRIER_EXPECT_TX(addr, bytes) \
    asm volatile("mbarrier.arrive.expect_tx.shared.b64 _, [%0], %1;" :: "r"((uint32_t)(addr)), "r"((uint32_t)(bytes)) : "memory")
#define MBARRIER_ARRIVE(addr) \
    asm volatile("mbarrier.arrive.shared.b64 _, [%0];" :: "r"((uint32_t)(addr)) : "memory")
#define FENCE_PROXY_ASYNC() asm volatile("fence.proxy.async.shared::cta;" ::: "memory")

#define MBARRIER_WAIT_PARITY(mbar_smem_addr, phase_parity) do { \
    uint32_t _mbar = (uint32_t)(mbar_smem_addr); \
    uint32_t _parity = (uint32_t)(phase_parity); \
    uint32_t _done; \
    asm volatile( \
        "{\n\t.reg .pred p;\n\t" \
        "mbarrier.try_wait.parity.acquire.cta.shared::cta.b64 p, [%1], %2;\n\t" \
        "selp.b32 %0, 1, 0, p;\n\t}" \
        : "=r"(_done) : "r"(_mbar), "r"(_parity) : "memory"); \
    if (!_done) { \
        asm volatile( \
            "{\n\t.reg .pred P1;\n\t" \
            "WAIT_LOOP_%=:\n\t" \
            "mbarrier.try_wait.parity.acquire.cta.shared::cta.b64 P1, [%0], %1, 0x989680;\n\t" \
            "@P1 bra.uni WAIT_DONE_%=;\n\t" \
            "bra.uni WAIT_LOOP_%=;\n\t" \
            "WAIT_DONE_%=:\n\t}" \
            :: "r"(_mbar), "r"(_parity) : "memory"); \
    } \
} while (0)

__device__ __forceinline__ void tma2d(uint32_t dst, const CUtensorMap* map,
                                      int x, int y, uint32_t mbar) {
    asm volatile(
        "cp.async.bulk.tensor.2d.shared::cta.global.tile.mbarrier::complete_tx::bytes "
        "[%0], [%1, {%2, %3}], [%4];"
        :: "r"(dst), "l"(map), "r"(x), "r"(y), "r"(mbar) : "memory");
}

__device__ __forceinline__ void ldsm4(uint32_t* r, uint32_t addr) {
    asm volatile("ldmatrix.sync.aligned.m8n8.x4.shared.b16 {%0,%1,%2,%3}, [%4];"
                 : "=r"(r[0]), "=r"(r[1]), "=r"(r[2]), "=r"(r[3]) : "r"(addr));
}

__device__ __forceinline__ void mma16816(float* c, const uint32_t* a,
                                         uint32_t b0, uint32_t b1) {
    asm volatile(
        "mma.sync.aligned.m16n8k16.row.col.f32.f16.f16.f32 "
        "{%0,%1,%2,%3}, {%4,%5,%6,%7}, {%8,%9}, {%0,%1,%2,%3};"
        : "+f"(c[0]), "+f"(c[1]), "+f"(c[2]), "+f"(c[3])
        : "r"(a[0]), "r"(a[1]), "r"(a[2]), "r"(a[3]), "r"(b0), "r"(b1));
}

// ---------------------------------------------------------------------------
// Kernel 1: bucket batch rows by layer id. Output values are order-independent.
// ---------------------------------------------------------------------------
__global__ void bucketize_kernel(const int* __restrict__ layer_ids) {
    __shared__ int s_cnt[NL];
    __shared__ int s_cur[NL];
    int t = threadIdx.x;
    if (t < NL) s_cnt[t] = 0;
    __syncthreads();
    for (int b = t; b < NB; b += blockDim.x)
        atomicAdd(&s_cnt[layer_ids[b]], 1);
    __syncthreads();
    if (t == 0) {
        int off = 0;
        for (int l = 0; l < NL; l++) {
            s_cur[l] = off;
            g_offset[l] = off;
            g_count[l] = s_cnt[l];
            off += s_cnt[l];
        }
    }
    __syncthreads();
    for (int b = t; b < NB; b += blockDim.x) {
        int l = layer_ids[b];
        int pos = atomicAdd(&s_cur[l], 1);
        g_perm[pos] = b;
    }
}

// ---------------------------------------------------------------------------
// Kernel 2: E = W - I, fp32 -> fp16. E ~ 0.02-scale so fp16 quant error is
// ~0.02 * 2^-12 per element. Pure bandwidth (64 MB read + 32 MB write).
// ---------------------------------------------------------------------------
__global__ __launch_bounds__(256) void convert_e_kernel(const float* __restrict__ w) {
    int i = blockIdx.x * 256 + threadIdx.x;              // float4 index
    float4 v = reinterpret_cast<const float4*>(w)[i];
    size_t e0 = (size_t)i * 4;
    int row  = (int)((e0 >> 10) & (NH - 1));             // i within layer (NH=1024)
    int col0 = (int)(e0 & (NH - 1));                     // j of first element
    float x[4] = {v.x, v.y, v.z, v.w};
#pragma unroll
    for (int j = 0; j < 4; j++)
        if (row == col0 + j) x[j] -= 1.0f;
    __half2 p01 = __halves2half2(__float2half_rn(x[0]), __float2half_rn(x[1]));
    __half2 p23 = __halves2half2(__float2half_rn(x[2]), __float2half_rn(x[3]));
    uint2 o;
    o.x = *reinterpret_cast<uint32_t*>(&p01);
    o.y = *reinterpret_cast<uint32_t*>(&p23);
    reinterpret_cast<uint2*>(g_e)[i] = o;
}

// ---------------------------------------------------------------------------
// Kernel 3: gather z into bucket order + convert to fp16.
// ---------------------------------------------------------------------------
__global__ __launch_bounds__(256) void convert_z_kernel(const float* __restrict__ z) {
    int i = blockIdx.x * 256 + threadIdx.x;              // float4 index
    int pos = i / (NH / 4);
    int c4  = i % (NH / 4);
    int src = g_perm[pos];
    float4 v = reinterpret_cast<const float4*>(z + (size_t)src * NH)[c4];
    __half2 p01 = __halves2half2(__float2half_rn(v.x), __float2half_rn(v.y));
    __half2 p23 = __halves2half2(__float2half_rn(v.z), __float2half_rn(v.w));
    uint2 o;
    o.x = *reinterpret_cast<uint32_t*>(&p01);
    o.y = *reinterpret_cast<uint32_t*>(&p23);
    reinterpret_cast<uint2*>(g_z)[i] = o;
}

// ---------------------------------------------------------------------------
// Kernel 4: grouped mma.sync GEMM computing acc = E @ z (single fp16 term),
// TMA 5-stage pipeline. CTA tile 128x128, 512 threads, 16 warps (4m x 4n),
// warp tile 32x32. Epilogue: out = acc + z_fp32 + bias (exact z passthrough).
// ---------------------------------------------------------------------------
__device__ __forceinline__ void issue_chunk(
    uint32_t sb, int s, int c,
    const CUtensorMap* mZ, const CUtensorMap* mE,
    int aRow0, int bRow0)
{
    const uint32_t mb = sb + 8u * s;                       // full[s]
    const uint32_t st = sb + SMEM_STAGE0 + (uint32_t)s * STAGE_BYTES;
    MBARRIER_EXPECT_TX(mb, (uint32_t)STAGE_BYTES);         // 32768 bytes
    const int x = c * KC;
    tma2d(st + OFF_A, mZ, x, aRow0, mb);
    tma2d(st + OFF_B, mE, x, bRow0, mb);
}

__global__ __launch_bounds__(512, 1) void gemm_kernel(
    const __grid_constant__ CUtensorMap mZ,
    const __grid_constant__ CUtensorMap mE,
    const float* __restrict__ bias,
    const float* __restrict__ zfull,
    float* __restrict__ out)
{
    const int l  = blockIdx.y >> 5;
    const int mt = blockIdx.y & 31;
    const int count = g_count[l];
    const int m0 = mt * BM;
    if (m0 >= count) return;
    const int off = g_offset[l];
    const int n0 = blockIdx.x * BN;

    extern __shared__ char smem[];
    const uint32_t sb = smem_u32(smem);
    const int tid  = threadIdx.x;
    const int lane = tid & 31;
    const int wid  = tid >> 5;
    const int wm   = wid >> 2;     // 0..3 (m dimension)
    const int wn   = wid & 3;      // 0..3 (n dimension)

    if (tid == 0) {
#pragma unroll
        for (int s = 0; s < NSTAGE; s++) {
            MBARRIER_INIT(sb + 8 * s, 1);         // full[s]
            MBARRIER_INIT(sb + 64 + 8 * s, 16);   // empty[s]
        }
        FENCE_PROXY_ASYNC();
    }
    __syncthreads();

    const int aRow0 = off + m0;          // z rows (bucket-gathered; TMA zero-fills OOB)
    const int bRow0 = l * NH + n0;       // E rows

    if (tid == 0) {
#pragma unroll
        for (int s = 0; s < NSTAGE; s++)
            issue_chunk(sb, s, s, &mZ, &mE, aRow0, bRow0);
    }

    // ldmatrix per-lane address components
    const int aRow = (lane & 7) + ((lane >> 3) & 1) * 8;   // row within m16 tile
    const int aK   = ((lane >> 4) & 1) * 16;               // 16B k-subchunk
    const int bRow = (lane & 7) + ((lane >> 4) & 1) * 8;   // row within n16 pair
    const int bK   = ((lane >> 3) & 1) * 16;

    float acc[2][4][4];
#pragma unroll
    for (int i = 0; i < 2; i++)
#pragma unroll
        for (int j = 0; j < 4; j++)
#pragma unroll
            for (int r = 0; r < 4; r++) acc[i][j][r] = 0.0f;

#pragma unroll 1
    for (int c = 0; c < NCHUNK; c++) {
        const int s  = c % NSTAGE;
        const int ph = (c / NSTAGE) & 1;
        MBARRIER_WAIT_PARITY(sb + 8 * s, ph);

        const uint32_t st = sb + SMEM_STAGE0 + (uint32_t)s * STAGE_BYTES;
#pragma unroll
        for (int ks = 0; ks < 4; ks++) {
            const uint32_t kb = ks * 32;
            uint32_t bh[8];
#pragma unroll
            for (int jj = 0; jj < 2; jj++) {
                uint32_t o = (uint32_t)(32 * wn + 16 * jj + bRow) * 128 + kb + bK;
                ldsm4(&bh[jj * 4], st + OFF_B + SW128(o));
            }
#pragma unroll
            for (int i = 0; i < 2; i++) {
                uint32_t o = (uint32_t)(32 * wm + 16 * i + aRow) * 128 + kb + aK;
                uint32_t ah[4];
                ldsm4(ah, st + OFF_A + SW128(o));
#pragma unroll
                for (int j = 0; j < 4; j++) {
                    const int bi = (j >> 1) * 4 + (j & 1) * 2;
                    mma16816(acc[i][j], ah, bh[bi], bh[bi + 1]);   // E * z
                }
            }
        }

        // This warp is done reading stage s for chunk c.
        if (lane == 0) MBARRIER_ARRIVE(sb + 64 + 8 * s);

        // Producer: refill stage s with chunk c+NSTAGE once all 16 warps arrived.
        if (tid == 0 && c + NSTAGE < NCHUNK) {
            MBARRIER_WAIT_PARITY(sb + 64 + 8 * s, ph);
            issue_chunk(sb, s, c + NSTAGE, &mZ, &mE, aRow0, bRow0);
        }
    }

    // Epilogue: out = acc + z_fp32 (exact identity passthrough) + bias; scatter.
    const int colBase = n0 + 32 * wn + (lane & 3) * 2;
    const float* bias_l = bias + (size_t)l * NH;
    float2 bb[4];
#pragma unroll
    for (int j = 0; j < 4; j++)
        bb[j] = *reinterpret_cast<const float2*>(bias_l + colBase + 8 * j);

    const int rBase = m0 + 32 * wm + (lane >> 2);
#pragma unroll
    for (int i = 0; i < 2; i++) {
#pragma unroll
        for (int half = 0; half < 2; half++) {
            const int r = rBase + 16 * i + 8 * half;
            if (r < count) {
                const int orow = g_perm[off + r];
                const float* zp = zfull + (size_t)orow * NH;
                float* op = out + (size_t)orow * NH;
#pragma unroll
                for (int j = 0; j < 4; j++) {
                    float2 zv = *reinterpret_cast<const float2*>(zp + colBase + 8 * j);
                    float2 v = {acc[i][j][2 * half + 0] + bb[j].x + zv.x,
                                acc[i][j][2 * half + 1] + bb[j].y + zv.y};
                    *reinterpret_cast<float2*>(op + colBase + 8 * j) = v;
                }
            }
        }
    }
}

// ---------------------------------------------------------------------------
// Launch
// ---------------------------------------------------------------------------
typedef CUresult (*PFN_tmapEncode)(
    CUtensorMap*, CUtensorMapDataType, cuuint32_t, void*,
    const cuuint64_t*, const cuuint64_t*, const cuuint32_t*, const cuuint32_t*,
    CUtensorMapInterleave, CUtensorMapSwizzle, CUtensorMapL2promotion,
    CUtensorMapFloatOOBfill);

extern "C" void kernel_launch(void* const* d_in, const int* in_sizes, int n_in,
                              void* d_out, int out_size) {
    const float* z         = (const float*)d_in[0];
    const int*   layer_ids = (const int*)d_in[1];
    const float* weight    = (const float*)d_in[2];
    const float* bias      = (const float*)d_in[3];
    float*       out       = (float*)d_out;

    static bool inited = false;
    static CUtensorMap mZ, mE;
    if (!inited) {
        PFN_tmapEncode enc = nullptr;
        cudaDriverEntryPointQueryResult qr;
        cudaGetDriverEntryPoint("cuTensorMapEncodeTiled", (void**)&enc,
                                cudaEnableDefault, &qr);
        void *pz, *pe;
        cudaGetSymbolAddress(&pz, g_z);
        cudaGetSymbolAddress(&pe, g_e);

        cuuint64_t zdims[2] = {NH, NB};
        cuuint64_t wdims[2] = {NH, (cuuint64_t)NL * NH};
        cuuint64_t strides[1] = {NH * 2};
        cuuint32_t zbox[2] = {KC, BM};
        cuuint32_t wbox[2] = {KC, BN};
        cuuint32_t es[2]  = {1, 1};

        enc(&mZ, CU_TENSOR_MAP_DATA_TYPE_FLOAT16, 2, pz, zdims, strides, zbox, es,
            CU_TENSOR_MAP_INTERLEAVE_NONE, CU_TENSOR_MAP_SWIZZLE_128B,
            CU_TENSOR_MAP_L2_PROMOTION_L2_128B, CU_TENSOR_MAP_FLOAT_OOB_FILL_NONE);
        enc(&mE, CU_TENSOR_MAP_DATA_TYPE_FLOAT16, 2, pe, wdims, strides, wbox, es,
            CU_TENSOR_MAP_INTERLEAVE_NONE, CU_TENSOR_MAP_SWIZZLE_128B,
            CU_TENSOR_MAP_L2_PROMOTION_L2_128B, CU_TENSOR_MAP_FLOAT_OOB_FILL_NONE);

        cudaFuncSetAttribute(gemm_kernel, cudaFuncAttributeMaxDynamicSharedMemorySize,
                             SMEM_DYN_TOTAL);
        inited = true;
    }

    bucketize_kernel<<<1, 256>>>(layer_ids);
    convert_z_kernel<<<(NB * NH / 4) / 256, 256>>>(z);
    convert_e_kernel<<<(int)(((size_t)NL * NH * NH / 4) / 256), 256>>>(weight);

    dim3 grid(NH / BN, NL * MT_MAX);
    gemm_kernel<<<grid, 512, SMEM_DYN_TOTAL>>>(mZ, mE, bias, z, out);
}

// round 9
// speedup vs baseline: 1.0782x; 1.0782x over previous
#include <cuda_runtime.h>
#include <cuda.h>
#include <cuda_fp16.h>
#include <cstdint>

#define NL 16
#define NB 4096
#define NH 1024
#define BM 128
#define BN 128
#define KC 64                 // fp16 elements per K chunk (= 128 bytes = SW128 row)
#define NCHUNK (NH / KC)      // 16
#define NSTAGE 2
#define MT_MAX (NB / BM)      // 32

#define STAGE_BYTES 32768     // A 16384 + B 16384
#define OFF_A  0
#define OFF_B  16384
#define SMEM_STAGE0 1024
#define SMEM_DYN_TOTAL (SMEM_STAGE0 + NSTAGE * STAGE_BYTES)   // 66560 -> 2 CTAs/SM

#define SW128(off) ((off) ^ (((off) >> 3) & 0x70))

// ------------------------- device scratch (no allocs) -----------------------
__device__ int g_count[NL];
__device__ int g_offset[NL];
__device__ int g_perm[NB];
__device__ __half g_e[(size_t)NL * NH * NH];   // 32 MB : E = W - I in fp16
__device__ __half g_z[(size_t)NB * NH];        // 8 MB  : bucket-gathered z fp16

// ------------------------------ PTX helpers ---------------------------------
__device__ __forceinline__ uint32_t smem_u32(const void* p) {
    uint32_t a;
    asm("{ .reg .u64 t; cvta.to.shared.u64 t, %1; cvt.u32.u64 %0, t; }" : "=r"(a) : "l"(p));
    return a;
}

#define MBARRIER_INIT(addr, cnt) \
    asm volatile("mbarrier.init.shared.b64 [%0], %1;" :: "r"((uint32_t)(addr)), "r"((uint32_t)(cnt)) : "memory")
#define MBARRIER_EXPECT_TX(addr, bytes) \
    asm volatile("mbarrier.arrive.expect_tx.shared.b64 _, [%0], %1;" :: "r"((uint32_t)(addr)), "r"((uint32_t)(bytes)) : "memory")
#define MBARRIER_ARRIVE(addr) \
    asm volatile("mbarrier.arrive.shared.b64 _, [%0];" :: "r"((uint32_t)(addr)) : "memory")
#define FENCE_PROXY_ASYNC() asm volatile("fence.proxy.async.shared::cta;" ::: "memory")

#define MBARRIER_WAIT_PARITY(mbar_smem_addr, phase_parity) do { \
    uint32_t _mbar = (uint32_t)(mbar_smem_addr); \
    uint32_t _parity = (uint32_t)(phase_parity); \
    uint32_t _done; \
    asm volatile( \
        "{\n\t.reg .pred p;\n\t" \
        "mbarrier.try_wait.parity.acquire.cta.shared::cta.b64 p, [%1], %2;\n\t" \
        "selp.b32 %0, 1, 0, p;\n\t}" \
        : "=r"(_done) : "r"(_mbar), "r"(_parity) : "memory"); \
    if (!_done) { \
        asm volatile( \
            "{\n\t.reg .pred P1;\n\t" \
            "WAIT_LOOP_%=:\n\t" \
            "mbarrier.try_wait.parity.acquire.cta.shared::cta.b64 P1, [%0], %1, 0x989680;\n\t" \
            "@P1 bra.uni WAIT_DONE_%=;\n\t" \
            "bra.uni WAIT_LOOP_%=;\n\t" \
            "WAIT_DONE_%=:\n\t}" \
            :: "r"(_mbar), "r"(_parity) : "memory"); \
    } \
} while (0)

__device__ __forceinline__ void tma2d(uint32_t dst, const CUtensorMap* map,
                                      int x, int y, uint32_t mbar) {
    asm volatile(
        "cp.async.bulk.tensor.2d.shared::cta.global.tile.mbarrier::complete_tx::bytes "
        "[%0], [%1, {%2, %3}], [%4];"
        :: "r"(dst), "l"(map), "r"(x), "r"(y), "r"(mbar) : "memory");
}

__device__ __forceinline__ void ldsm4(uint32_t* r, uint32_t addr) {
    asm volatile("ldmatrix.sync.aligned.m8n8.x4.shared.b16 {%0,%1,%2,%3}, [%4];"
                 : "=r"(r[0]), "=r"(r[1]), "=r"(r[2]), "=r"(r[3]) : "r"(addr));
}

__device__ __forceinline__ void mma16816(float* c, const uint32_t* a,
                                         uint32_t b0, uint32_t b1) {
    asm volatile(
        "mma.sync.aligned.m16n8k16.row.col.f32.f16.f16.f32 "
        "{%0,%1,%2,%3}, {%4,%5,%6,%7}, {%8,%9}, {%0,%1,%2,%3};"
        : "+f"(c[0]), "+f"(c[1]), "+f"(c[2]), "+f"(c[3])
        : "r"(a[0]), "r"(a[1]), "r"(a[2]), "r"(a[3]), "r"(b0), "r"(b1));
}

// ---------------------------------------------------------------------------
// Kernel 1: bucket batch rows by layer id. Output values are order-independent.
// ---------------------------------------------------------------------------
__global__ void bucketize_kernel(const int* __restrict__ layer_ids) {
    __shared__ int s_cnt[NL];
    __shared__ int s_cur[NL];
    int t = threadIdx.x;
    if (t < NL) s_cnt[t] = 0;
    __syncthreads();
    for (int b = t; b < NB; b += blockDim.x)
        atomicAdd(&s_cnt[layer_ids[b]], 1);
    __syncthreads();
    if (t == 0) {
        int off = 0;
        for (int l = 0; l < NL; l++) {
            s_cur[l] = off;
            g_offset[l] = off;
            g_count[l] = s_cnt[l];
            off += s_cnt[l];
        }
    }
    __syncthreads();
    for (int b = t; b < NB; b += blockDim.x) {
        int l = layer_ids[b];
        int pos = atomicAdd(&s_cur[l], 1);
        g_perm[pos] = b;
    }
}

// ---------------------------------------------------------------------------
// Kernel 2: E = W - I, fp32 -> fp16. E ~ 0.02-scale so fp16 quant error is
// ~0.02 * 2^-12 per element. Pure bandwidth (64 MB read + 32 MB write).
// ---------------------------------------------------------------------------
__global__ __launch_bounds__(256) void convert_e_kernel(const float* __restrict__ w) {
    int i = blockIdx.x * 256 + threadIdx.x;              // float4 index
    float4 v = reinterpret_cast<const float4*>(w)[i];
    size_t e0 = (size_t)i * 4;
    int row  = (int)((e0 >> 10) & (NH - 1));             // i within layer (NH=1024)
    int col0 = (int)(e0 & (NH - 1));                     // j of first element
    float x[4] = {v.x, v.y, v.z, v.w};
#pragma unroll
    for (int j = 0; j < 4; j++)
        if (row == col0 + j) x[j] -= 1.0f;
    __half2 p01 = __halves2half2(__float2half_rn(x[0]), __float2half_rn(x[1]));
    __half2 p23 = __halves2half2(__float2half_rn(x[2]), __float2half_rn(x[3]));
    uint2 o;
    o.x = *reinterpret_cast<uint32_t*>(&p01);
    o.y = *reinterpret_cast<uint32_t*>(&p23);
    reinterpret_cast<uint2*>(g_e)[i] = o;
}

// ---------------------------------------------------------------------------
// Kernel 3: gather z into bucket order + convert to fp16.
// ---------------------------------------------------------------------------
__global__ __launch_bounds__(256) void convert_z_kernel(const float* __restrict__ z) {
    int i = blockIdx.x * 256 + threadIdx.x;              // float4 index
    int pos = i / (NH / 4);
    int c4  = i % (NH / 4);
    int src = g_perm[pos];
    float4 v = reinterpret_cast<const float4*>(z + (size_t)src * NH)[c4];
    __half2 p01 = __halves2half2(__float2half_rn(v.x), __float2half_rn(v.y));
    __half2 p23 = __halves2half2(__float2half_rn(v.z), __float2half_rn(v.w));
    uint2 o;
    o.x = *reinterpret_cast<uint32_t*>(&p01);
    o.y = *reinterpret_cast<uint32_t*>(&p23);
    reinterpret_cast<uint2*>(g_z)[i] = o;
}

// ---------------------------------------------------------------------------
// Kernel 4: grouped mma.sync GEMM computing acc = E @ z (single fp16 term),
// TMA 2-stage pipeline, 2 CTAs/SM, ~1 full wave. CTA tile 128x128, 8 warps
// (2m x 4n), warp tile 64x32 (16 independent MMAs per k-step for ILP).
// Epilogue: out = acc + z_fp32 + bias (exact z passthrough), scatter by perm.
// ---------------------------------------------------------------------------
__device__ __forceinline__ void issue_chunk(
    uint32_t sb, int s, int c,
    const CUtensorMap* mZ, const CUtensorMap* mE,
    int aRow0, int bRow0)
{
    const uint32_t mb = sb + 8u * s;                       // full[s]
    const uint32_t st = sb + SMEM_STAGE0 + (uint32_t)s * STAGE_BYTES;
    MBARRIER_EXPECT_TX(mb, (uint32_t)STAGE_BYTES);         // 32768 bytes
    const int x = c * KC;
    tma2d(st + OFF_A, mZ, x, aRow0, mb);
    tma2d(st + OFF_B, mE, x, bRow0, mb);
}

__global__ __launch_bounds__(256, 2) void gemm_kernel(
    const __grid_constant__ CUtensorMap mZ,
    const __grid_constant__ CUtensorMap mE,
    const float* __restrict__ bias,
    const float* __restrict__ zfull,
    float* __restrict__ out)
{
    const int l  = blockIdx.y >> 5;
    const int mt = blockIdx.y & 31;
    const int count = g_count[l];
    const int m0 = mt * BM;
    if (m0 >= count) return;
    const int off = g_offset[l];
    const int n0 = blockIdx.x * BN;

    extern __shared__ char smem[];
    const uint32_t sb = smem_u32(smem);
    const int tid  = threadIdx.x;
    const int lane = tid & 31;
    const int wid  = tid >> 5;
    const int wm   = wid >> 2;     // 0..1 (m dimension, 64 rows each)
    const int wn   = wid & 3;      // 0..3 (n dimension, 32 cols each)

    if (tid == 0) {
#pragma unroll
        for (int s = 0; s < NSTAGE; s++) {
            MBARRIER_INIT(sb + 8 * s, 1);        // full[s]
            MBARRIER_INIT(sb + 32 + 8 * s, 8);   // empty[s]
        }
        FENCE_PROXY_ASYNC();
    }
    __syncthreads();

    const int aRow0 = off + m0;          // z rows (bucket-gathered; TMA zero-fills OOB)
    const int bRow0 = l * NH + n0;       // E rows

    if (tid == 0) {
        issue_chunk(sb, 0, 0, &mZ, &mE, aRow0, bRow0);
        issue_chunk(sb, 1, 1, &mZ, &mE, aRow0, bRow0);
    }

    // ldmatrix per-lane address components
    const int aRow = (lane & 7) + ((lane >> 3) & 1) * 8;   // row within m16 tile
    const int aK   = ((lane >> 4) & 1) * 16;               // 16B k-subchunk
    const int bRow = (lane & 7) + ((lane >> 4) & 1) * 8;   // row within n16 pair
    const int bK   = ((lane >> 3) & 1) * 16;

    float acc[4][4][4];
#pragma unroll
    for (int i = 0; i < 4; i++)
#pragma unroll
        for (int j = 0; j < 4; j++)
#pragma unroll
            for (int r = 0; r < 4; r++) acc[i][j][r] = 0.0f;

#pragma unroll 1
    for (int c = 0; c < NCHUNK; c++) {
        const int s  = c & 1;
        const int ph = (c >> 1) & 1;
        MBARRIER_WAIT_PARITY(sb + 8 * s, ph);

        const uint32_t st = sb + SMEM_STAGE0 + (uint32_t)s * STAGE_BYTES;
#pragma unroll
        for (int ks = 0; ks < 4; ks++) {
            const uint32_t kb = ks * 32;
            uint32_t bh[8];
#pragma unroll
            for (int jj = 0; jj < 2; jj++) {
                uint32_t o = (uint32_t)(32 * wn + 16 * jj + bRow) * 128 + kb + bK;
                ldsm4(&bh[jj * 4], st + OFF_B + SW128(o));
            }
            uint32_t ah[4][4];
#pragma unroll
            for (int i = 0; i < 4; i++) {
                uint32_t o = (uint32_t)(64 * wm + 16 * i + aRow) * 128 + kb + aK;
                ldsm4(ah[i], st + OFF_A + SW128(o));
            }
#pragma unroll
            for (int i = 0; i < 4; i++)
#pragma unroll
                for (int j = 0; j < 4; j++) {
                    const int bi = (j >> 1) * 4 + (j & 1) * 2;
                    mma16816(acc[i][j], ah[i], bh[bi], bh[bi + 1]);   // E * z
                }
        }

        // This warp is done reading stage s for chunk c.
        if (lane == 0) MBARRIER_ARRIVE(sb + 32 + 8 * s);

        // Producer: refill stage s with chunk c+2 once all 8 warps arrived.
        if (tid == 0 && c + 2 < NCHUNK) {
            MBARRIER_WAIT_PARITY(sb + 32 + 8 * s, ph);
            issue_chunk(sb, s, c + 2, &mZ, &mE, aRow0, bRow0);
        }
    }

    // Epilogue: out = acc + z_fp32 (exact identity passthrough) + bias; scatter.
    const int colBase = n0 + 32 * wn + (lane & 3) * 2;
    const float* bias_l = bias + (size_t)l * NH;
    float2 bb[4];
#pragma unroll
    for (int j = 0; j < 4; j++)
        bb[j] = *reinterpret_cast<const float2*>(bias_l + colBase + 8 * j);

    const int rBase = m0 + 64 * wm + (lane >> 2);
#pragma unroll
    for (int i = 0; i < 4; i++) {
#pragma unroll
        for (int half = 0; half < 2; half++) {
            const int r = rBase + 16 * i + 8 * half;
            if (r < count) {
                const int orow = g_perm[off + r];
                const float* zp = zfull + (size_t)orow * NH;
                float* op = out + (size_t)orow * NH;
#pragma unroll
                for (int j = 0; j < 4; j++) {
                    float2 zv = *reinterpret_cast<const float2*>(zp + colBase + 8 * j);
                    float2 v = {acc[i][j][2 * half + 0] + bb[j].x + zv.x,
                                acc[i][j][2 * half + 1] + bb[j].y + zv.y};
                    *reinterpret_cast<float2*>(op + colBase + 8 * j) = v;
                }
            }
        }
    }
}

// ---------------------------------------------------------------------------
// Launch
// ---------------------------------------------------------------------------
typedef CUresult (*PFN_tmapEncode)(
    CUtensorMap*, CUtensorMapDataType, cuuint32_t, void*,
    const cuuint64_t*, const cuuint64_t*, const cuuint32_t*, const cuuint32_t*,
    CUtensorMapInterleave, CUtensorMapSwizzle, CUtensorMapL2promotion,
    CUtensorMapFloatOOBfill);

extern "C" void kernel_launch(void* const* d_in, const int* in_sizes, int n_in,
                              void* d_out, int out_size) {
    const float* z         = (const float*)d_in[0];
    const int*   layer_ids = (const int*)d_in[1];
    const float* weight    = (const float*)d_in[2];
    const float* bias      = (const float*)d_in[3];
    float*       out       = (float*)d_out;

    static bool inited = false;
    static CUtensorMap mZ, mE;
    if (!inited) {
        PFN_tmapEncode enc = nullptr;
        cudaDriverEntryPointQueryResult qr;
        cudaGetDriverEntryPoint("cuTensorMapEncodeTiled", (void**)&enc,
                                cudaEnableDefault, &qr);
        void *pz, *pe;
        cudaGetSymbolAddress(&pz, g_z);
        cudaGetSymbolAddress(&pe, g_e);

        cuuint64_t zdims[2] = {NH, NB};
        cuuint64_t wdims[2] = {NH, (cuuint64_t)NL * NH};
        cuuint64_t strides[1] = {NH * 2};
        cuuint32_t zbox[2] = {KC, BM};
        cuuint32_t wbox[2] = {KC, BN};
        cuuint32_t es[2]  = {1, 1};

        enc(&mZ, CU_TENSOR_MAP_DATA_TYPE_FLOAT16, 2, pz, zdims, strides, zbox, es,
            CU_TENSOR_MAP_INTERLEAVE_NONE, CU_TENSOR_MAP_SWIZZLE_128B,
            CU_TENSOR_MAP_L2_PROMOTION_L2_128B, CU_TENSOR_MAP_FLOAT_OOB_FILL_NONE);
        enc(&mE, CU_TENSOR_MAP_DATA_TYPE_FLOAT16, 2, pe, wdims, strides, wbox, es,
            CU_TENSOR_MAP_INTERLEAVE_NONE, CU_TENSOR_MAP_SWIZZLE_128B,
            CU_TENSOR_MAP_L2_PROMOTION_L2_128B, CU_TENSOR_MAP_FLOAT_OOB_FILL_NONE);

        cudaFuncSetAttribute(gemm_kernel, cudaFuncAttributeMaxDynamicSharedMemorySize,
                             SMEM_DYN_TOTAL);
        inited = true;
    }

    bucketize_kernel<<<1, 256>>>(layer_ids);
    convert_z_kernel<<<(NB * NH / 4) / 256, 256>>>(z);
    convert_e_kernel<<<(int)(((size_t)NL * NH * NH / 4) / 256), 256>>>(weight);

    dim3 grid(NH / BN, NL * MT_MAX);
    gemm_kernel<<<grid, 256, SMEM_DYN_TOTAL>>>(mZ, mE, bias, z, out);
}